// round 9
// baseline (speedup 1.0000x reference)
#include <cuda_runtime.h>
#include <cuda_bf16.h>
#include <math.h>
#include <cstdint>

#define Bb 16
#define Tt 256
#define Ee 512
#define Hh 1024
#define Vv 32000
#define G3 3072
#define Mm (Bb*Tt)   // 4096

#define GRU_BLOCKS 128

// ---- scratch ----
__device__ float g_gi[(size_t)Mm*G3];
__device__ float g_hs[(size_t)Mm*Hh];
__device__ __nv_bfloat16 g_W1b[(size_t)Hh*Hh];
__device__ __nv_bfloat16 g_W2b[(size_t)Vv*Hh];
__device__ __nv_bfloat16 g_hsb[(size_t)Mm*Hh];
__device__ __nv_bfloat16 g_yb [(size_t)Mm*Hh];
__device__ int g_flags[GRU_BLOCKS * 8];
__device__ int g_gen;

__device__ __forceinline__ uint32_t smem_u32(const void* p) {
    uint32_t a;
    asm("{ .reg .u64 t; cvta.to.shared.u64 t, %1; cvt.u32.u64 %0, t; }" : "=r"(a) : "l"(p));
    return a;
}
__device__ __forceinline__ void fma2(unsigned long long& d, unsigned long long a, unsigned long long b) {
    asm("fma.rn.f32x2 %0, %1, %2, %0;" : "+l"(d) : "l"(a), "l"(b));
}
__device__ __forceinline__ float sum2(unsigned long long v) {
    float lo, hi;
    asm("mov.b64 {%0, %1}, %2;" : "=f"(lo), "=f"(hi) : "l"(v));
    return lo + hi;
}

// ================= fp32 -> bf16 (weights only) =================
__global__ void f2bf_kernel(const float* __restrict__ x, __nv_bfloat16* __restrict__ o, int n4)
{
    int i = blockIdx.x * blockDim.x + threadIdx.x;
    if (i >= n4) return;
    float4 v = ((const float4*)x)[i];
    __nv_bfloat162* p = (__nv_bfloat162*)o + i * 2;
    p[0] = __floats2bfloat162_rn(v.x, v.y);
    p[1] = __floats2bfloat162_rn(v.z, v.w);
}

// ================= HMMA bf16 GEMM, 3-stage cp.async (R7 config) =================
#define HG_STRIDE  40
#define HG_ATILE   (128 * HG_STRIDE * 2)    // 10240 B
#define HG_STAGE   (2 * HG_ATILE)           // 20480 B
#define HG_NSTG    3
#define HG_SMEM    (HG_NSTG * HG_STAGE)     // 61440 B

__device__ __forceinline__ void ldsm_x4(uint32_t* r, uint32_t addr) {
    asm volatile("ldmatrix.sync.aligned.m8n8.x4.shared.b16 {%0,%1,%2,%3}, [%4];"
                 : "=r"(r[0]), "=r"(r[1]), "=r"(r[2]), "=r"(r[3]) : "r"(addr));
}
__device__ __forceinline__ void mma16816(float* d, const uint32_t* a, uint32_t b0, uint32_t b1) {
    asm volatile("mma.sync.aligned.m16n8k16.row.col.f32.bf16.bf16.f32 "
                 "{%0,%1,%2,%3}, {%4,%5,%6,%7}, {%8,%9}, {%0,%1,%2,%3};"
                 : "+f"(d[0]), "+f"(d[1]), "+f"(d[2]), "+f"(d[3])
                 : "r"(a[0]), "r"(a[1]), "r"(a[2]), "r"(a[3]), "r"(b0), "r"(b1));
}
__device__ __forceinline__ void cp_async16(uint32_t saddr, const void* gaddr) {
    asm volatile("cp.async.cg.shared.global [%0], [%1], 16;" :: "r"(saddr), "l"(gaddr));
}

__global__ void __launch_bounds__(256) hmma_gemm_kernel(
    const __nv_bfloat16* __restrict__ A,
    const __nv_bfloat16* __restrict__ Bm,
    const float* __restrict__ bias,
    void* __restrict__ Cv,
    int M, int N, int K, int do_relu, int out_bf16)
{
    extern __shared__ char smem[];
    const uint32_t sb = smem_u32(smem);
    const int tid  = threadIdx.x;
    const int wid  = tid >> 5;
    const int lane = tid & 31;
    const int bn = blockIdx.x, bm = blockIdx.y;

    const int warp_m = wid & 3;
    const int warp_n = wid >> 2;

    float d[2][8][4];
#pragma unroll
    for (int i = 0; i < 2; i++)
#pragma unroll
        for (int j = 0; j < 8; j++)
#pragma unroll
            for (int q = 0; q < 4; q++) d[i][j][q] = 0.f;

    const int NK = K >> 5;
    const int lmat = lane >> 3;
    const int lrow = lane & 7;

    auto load_stage = [&](int it, int buf) {
        const int kt = it << 5;
        const uint32_t sa = sb + buf * HG_STAGE;
        const uint32_t sbB = sa + HG_ATILE;
#pragma unroll
        for (int s = 0; s < 2; s++) {
            const int idx = tid + s * 256;
            const int row = idx >> 2, c = idx & 3;
            cp_async16(sa + row * (HG_STRIDE*2) + c * 16,
                       A + (size_t)(bm * 128 + row) * K + kt + c * 8);
            cp_async16(sbB + row * (HG_STRIDE*2) + c * 16,
                       Bm + (size_t)(bn * 128 + row) * K + kt + c * 8);
        }
        asm volatile("cp.async.commit_group;");
    };

    load_stage(0, 0);
    load_stage(1, 1);

    for (int it = 0; it < NK; it++) {
        asm volatile("cp.async.wait_group 1;");
        __syncthreads();
        if (it + 2 < NK) load_stage(it + 2, (it + 2) % HG_NSTG);

        const uint32_t sa  = sb + (it % HG_NSTG) * HG_STAGE;
        const uint32_t sbB = sa + HG_ATILE;

#pragma unroll
        for (int ks = 0; ks < 2; ks++) {
            uint32_t a[2][4];
#pragma unroll
            for (int mt = 0; mt < 2; mt++) {
                const int row = warp_m * 32 + mt * 16 + (lmat & 1) * 8 + lrow;
                const int c   = ks * 2 + (lmat >> 1);
                ldsm_x4(a[mt], sa + row * (HG_STRIDE*2) + c * 16);
            }
            uint32_t b[4][4];
#pragma unroll
            for (int nt = 0; nt < 4; nt++) {
                const int n = warp_n * 64 + nt * 16 + (lmat >> 1) * 8 + lrow;
                const int c = ks * 2 + (lmat & 1);
                ldsm_x4(b[nt], sbB + n * (HG_STRIDE*2) + c * 16);
            }
#pragma unroll
            for (int mt = 0; mt < 2; mt++)
#pragma unroll
                for (int nt = 0; nt < 4; nt++) {
                    mma16816(d[mt][nt*2+0], a[mt], b[nt][0], b[nt][1]);
                    mma16816(d[mt][nt*2+1], a[mt], b[nt][2], b[nt][3]);
                }
        }
    }

#pragma unroll
    for (int mt = 0; mt < 2; mt++) {
        const int row0 = bm * 128 + warp_m * 32 + mt * 16 + (lane >> 2);
#pragma unroll
        for (int nt8 = 0; nt8 < 8; nt8++) {
            const int col = bn * 128 + warp_n * 64 + nt8 * 8 + (lane & 3) * 2;
            const float b0 = bias[col], b1 = bias[col + 1];
            float2 v0, v1;
            v0.x = d[mt][nt8][0] + b0; v0.y = d[mt][nt8][1] + b1;
            v1.x = d[mt][nt8][2] + b0; v1.y = d[mt][nt8][3] + b1;
            if (do_relu) {
                v0.x = fmaxf(v0.x, 0.f); v0.y = fmaxf(v0.y, 0.f);
                v1.x = fmaxf(v1.x, 0.f); v1.y = fmaxf(v1.y, 0.f);
            }
            if (out_bf16) {
                __nv_bfloat162* C = (__nv_bfloat162*)Cv;
                C[((size_t)row0 * N + col) >> 1]       = __floats2bfloat162_rn(v0.x, v0.y);
                C[((size_t)(row0 + 8) * N + col) >> 1] = __floats2bfloat162_rn(v1.x, v1.y);
            } else {
                float* C = (float*)Cv;
                *(float2*)(C + (size_t)row0 * N + col)       = v0;
                *(float2*)(C + (size_t)(row0 + 8) * N + col) = v1;
            }
        }
    }
}

// ================= fp32 SIMT SGEMM (gi, gathered A) =================
__global__ void sgemm_kernel(const float* __restrict__ A,
                             const float* __restrict__ Bm,
                             const float* __restrict__ bias,
                             float* __restrict__ C,
                             int M, int N, int K,
                             const int* __restrict__ gidx,
                             int do_relu)
{
    __shared__ float As[8][128];
    __shared__ float Bs[8][128];

    const int tid = threadIdx.x;
    const int bn  = blockIdx.x;
    const int bm  = blockIdx.y;

    const int lrow = tid >> 1;
    const int kq   = (tid & 1) * 4;

    const int arow_g = bm * 128 + lrow;
    const float* Ap = gidx ? (A + (size_t)gidx[arow_g] * K)
                           : (A + (size_t)arow_g * K);
    const float* Bp = Bm + (size_t)(bn * 128 + lrow) * K;

    const int tx = tid & 15;
    const int ty = tid >> 4;
    const int m0 = ty * 8;
    const int n0 = tx * 8;

    float acc[8][8];
#pragma unroll
    for (int i = 0; i < 8; i++)
#pragma unroll
        for (int j = 0; j < 8; j++) acc[i][j] = 0.f;

    for (int kt = 0; kt < K; kt += 8) {
        float4 av = *(const float4*)(Ap + kt + kq);
        float4 bv = *(const float4*)(Bp + kt + kq);
        As[kq+0][lrow] = av.x; As[kq+1][lrow] = av.y;
        As[kq+2][lrow] = av.z; As[kq+3][lrow] = av.w;
        Bs[kq+0][lrow] = bv.x; Bs[kq+1][lrow] = bv.y;
        Bs[kq+2][lrow] = bv.z; Bs[kq+3][lrow] = bv.w;
        __syncthreads();

#pragma unroll
        for (int kk = 0; kk < 8; kk++) {
            float4 a0 = *(const float4*)&As[kk][m0];
            float4 a1 = *(const float4*)&As[kk][m0 + 4];
            float4 b0 = *(const float4*)&Bs[kk][n0];
            float4 b1 = *(const float4*)&Bs[kk][n0 + 4];
            float am[8] = {a0.x,a0.y,a0.z,a0.w,a1.x,a1.y,a1.z,a1.w};
            float bb[8] = {b0.x,b0.y,b0.z,b0.w,b1.x,b1.y,b1.z,b1.w};
#pragma unroll
            for (int i = 0; i < 8; i++)
#pragma unroll
                for (int j = 0; j < 8; j++)
                    acc[i][j] = fmaf(am[i], bb[j], acc[i][j]);
        }
        __syncthreads();
    }

    const int ncol0 = bn * 128 + n0;
    float bsv[8];
#pragma unroll
    for (int j = 0; j < 8; j++) bsv[j] = bias[ncol0 + j];

#pragma unroll
    for (int i = 0; i < 8; i++) {
        const int m = bm * 128 + m0 + i;
        float* crow = C + (size_t)m * N + ncol0;
#pragma unroll
        for (int jq = 0; jq < 2; jq++) {
            float4 v;
            v.x = acc[i][jq*4+0] + bsv[jq*4+0];
            v.y = acc[i][jq*4+1] + bsv[jq*4+1];
            v.z = acc[i][jq*4+2] + bsv[jq*4+2];
            v.w = acc[i][jq*4+3] + bsv[jq*4+3];
            if (do_relu) {
                v.x = fmaxf(v.x, 0.f); v.y = fmaxf(v.y, 0.f);
                v.z = fmaxf(v.z, 0.f); v.w = fmaxf(v.w, 0.f);
            }
            *(float4*)(crow + jq*4) = v;
        }
    }
}

// ================= persistent GRU, flag-based grid barrier (R7) =================
__global__ void __launch_bounds__(256) gru_persistent_kernel(
    const float* __restrict__ W_hh,
    const float* __restrict__ b_hh)
{
    extern __shared__ float smf[];
    float* W_s = smf;
    float* h_s = smf + 24*1024;

    const int tid  = threadIdx.x;
    const int w    = tid >> 5;
    const int lane = tid & 31;
    const int blk  = blockIdx.x;
    const int j    = blk * 8 + w;

    for (int idx = tid; idx < 24 * 256; idx += 256) {
        const int r = idx >> 8;
        const int q = idx & 255;
        const int g = r >> 3, wr = r & 7;
        *(float4*)&W_s[r*1024 + q*4] =
            *(const float4*)&W_hh[((size_t)(g*Hh + blk*8 + wr))*Hh + q*4];
    }
    for (int i = tid; i < Bb*Hh/4; i += 256)
        ((float4*)h_s)[i] = make_float4(0.f,0.f,0.f,0.f);
    __syncthreads();

    const float* wr_s = W_s + (0*8 + w) * 1024;
    const float* wz_s = W_s + (1*8 + w) * 1024;
    const float* wn_s = W_s + (2*8 + w) * 1024;
    const float bhr = b_hh[j], bhz = b_hh[j + Hh], bhn = b_hh[j + 2*Hh];

    for (int t = 0; t < Tt; t++) {
        float ir = 0.f, iz = 0.f, inn = 0.f;
        if (lane < 16) {
            const float* gi = g_gi + ((size_t)(lane*Tt + t)) * G3;
            ir  = __ldcg(gi + j);
            iz  = __ldcg(gi + j + Hh);
            inn = __ldcg(gi + j + 2*Hh);
        }

        unsigned long long ar2[16], az2[16], an2[16];
#pragma unroll
        for (int b = 0; b < 16; b++) { ar2[b] = 0ull; az2[b] = 0ull; an2[b] = 0ull; }

#pragma unroll 2
        for (int i = 0; i < 16; i++) {
            const int k2 = i*64 + lane*2;
            const unsigned long long vr = *(const unsigned long long*)&wr_s[k2];
            const unsigned long long vz = *(const unsigned long long*)&wz_s[k2];
            const unsigned long long vn = *(const unsigned long long*)&wn_s[k2];
#pragma unroll
            for (int b = 0; b < 16; b++) {
                const unsigned long long hv = *(const unsigned long long*)&h_s[b*Hh + k2];
                fma2(ar2[b], vr, hv);
                fma2(az2[b], vz, hv);
                fma2(an2[b], vn, hv);
            }
        }

        float ar[16], az[16], an[16];
#pragma unroll
        for (int b = 0; b < 16; b++) {
            ar[b] = sum2(ar2[b]);
            az[b] = sum2(az2[b]);
            an[b] = sum2(an2[b]);
        }

#pragma unroll
        for (int b = 0; b < 16; b++) {
#pragma unroll
            for (int o = 16; o > 0; o >>= 1) {
                ar[b] += __shfl_xor_sync(0xffffffffu, ar[b], o);
                az[b] += __shfl_xor_sync(0xffffffffu, az[b], o);
                an[b] += __shfl_xor_sync(0xffffffffu, an[b], o);
            }
        }

        if (lane < 16) {
            const int b = lane;
            const float r = 1.f / (1.f + expf(-(ir + ar[b] + bhr)));
            const float z = 1.f / (1.f + expf(-(iz + az[b] + bhz)));
            const float n = tanhf(inn + r * (an[b] + bhn));
            const float hp = h_s[b*Hh + j];
            const float h_new = (1.f - z)*n + z*hp;
            g_hs[((size_t)(b*Tt + t))*Hh + j] = h_new;
            g_hsb[((size_t)(b*Tt + t))*Hh + j] = __float2bfloat16(h_new);
        }

        if (t + 1 < Tt) {
            __syncthreads();
            if (tid == 0) {
                __threadfence();
                *(volatile int*)&g_flags[blk * 8] = t + 1;
            }
            if (blk == 0) {
                if (tid < GRU_BLOCKS) {
                    while (*(volatile int*)&g_flags[tid * 8] < t + 1) __nanosleep(32);
                }
                __syncthreads();
                if (tid == 0) { __threadfence(); *(volatile int*)&g_gen = t + 1; }
            } else {
                if (tid == 0) {
                    while (*(volatile int*)&g_gen < t + 1) __nanosleep(32);
                    __threadfence();
                }
                __syncthreads();
            }
            for (int i = tid*4; i < Bb*Hh; i += 256*4) {
                const int b = i >> 10;
                const int k = i & (Hh-1);
                *(float4*)&h_s[i] =
                    __ldcg((const float4*)&g_hs[((size_t)(b*Tt + t))*Hh + k]);
            }
            __syncthreads();
        }
    }

    __syncthreads();
    if (tid == 0) { __threadfence(); *(volatile int*)&g_flags[blk * 8] = 0; }
    if (blk == 0) {
        if (tid < GRU_BLOCKS) {
            while (*(volatile int*)&g_flags[tid * 8] != 0) __nanosleep(32);
        }
        __syncthreads();
        if (tid == 0) *(volatile int*)&g_gen = 0;
    }
}

// ================= fused log-softmax (in place) =================
__global__ void __launch_bounds__(256) logsoftmax_kernel(float* __restrict__ out)
{
    extern __shared__ float row_s[];
    const int row = blockIdx.x;
    const int tid = threadIdx.x;
    float* x = out + (size_t)row * Vv;

    float m = -INFINITY, s = 0.f;
    for (int v4 = tid; v4 < Vv/4; v4 += 256) {
        const float4 val = __ldcg((const float4*)x + v4);
        *((float4*)row_s + v4) = val;
        const float vm = fmaxf(fmaxf(val.x, val.y), fmaxf(val.z, val.w));
        if (vm > m) { s *= expf(m - vm); m = vm; }
        s += expf(val.x - m) + expf(val.y - m) + expf(val.z - m) + expf(val.w - m);
    }

    __shared__ float sm[256], ss[256];
    sm[tid] = m; ss[tid] = s;
    __syncthreads();
    for (int o = 128; o > 0; o >>= 1) {
        if (tid < o) {
            const float m2 = sm[tid + o], s2 = ss[tid + o];
            const float M_ = fmaxf(sm[tid], m2);
            ss[tid] = ss[tid]*expf(sm[tid]-M_) + s2*expf(m2-M_);
            sm[tid] = M_;
        }
        __syncthreads();
    }
    const float lse = sm[0] + logf(ss[0]);

    for (int v4 = tid; v4 < Vv/4; v4 += 256) {
        float4 val = *((float4*)row_s + v4);
        val.x -= lse; val.y -= lse; val.z -= lse; val.w -= lse;
        ((float4*)x)[v4] = val;
    }
}

__global__ void hidden_copy_kernel(float* __restrict__ out)
{
    const int i = blockIdx.x * blockDim.x + threadIdx.x;
    const int b = i >> 10;
    const int j = i & (Hh - 1);
    out[(size_t)Mm*Vv + i] = g_hs[((size_t)(b*Tt + Tt - 1))*Hh + j];
}

// ============================================================
extern "C" void kernel_launch(void* const* d_in, const int* in_sizes, int n_in,
                              void* d_out, int out_size)
{
    const int*   inputs = (const int*)  d_in[0];
    const float* emb    = (const float*)d_in[1];
    const float* W_ih   = (const float*)d_in[2];
    const float* W_hh   = (const float*)d_in[3];
    const float* b_ih   = (const float*)d_in[4];
    const float* b_hh   = (const float*)d_in[5];
    const float* W1     = (const float*)d_in[6];
    const float* b1     = (const float*)d_in[7];
    const float* W2     = (const float*)d_in[8];
    const float* b2     = (const float*)d_in[9];
    float* out = (float*)d_out;

    float *p_gi;
    __nv_bfloat16 *p_W1b, *p_W2b, *p_hsb, *p_yb;
    cudaGetSymbolAddress((void**)&p_gi,  g_gi);
    cudaGetSymbolAddress((void**)&p_W1b, g_W1b);
    cudaGetSymbolAddress((void**)&p_W2b, g_W2b);
    cudaGetSymbolAddress((void**)&p_hsb, g_hsb);
    cudaGetSymbolAddress((void**)&p_yb,  g_yb);

    const int gru_smem = (24*1024 + 16*1024) * 4;
    const int ls_smem  = Vv * 4;
    cudaFuncSetAttribute(gru_persistent_kernel,
                         cudaFuncAttributeMaxDynamicSharedMemorySize, gru_smem);
    cudaFuncSetAttribute(hmma_gemm_kernel,
                         cudaFuncAttributeMaxDynamicSharedMemorySize, HG_SMEM);
    cudaFuncSetAttribute(logsoftmax_kernel,
                         cudaFuncAttributeMaxDynamicSharedMemorySize, ls_smem);

    // 0) weight -> bf16
    f2bf_kernel<<<(Hh*Hh)/1024, 256>>>(W1, p_W1b, (Hh*Hh)/4);
    f2bf_kernel<<<((size_t)Vv*Hh)/1024, 256>>>(W2, p_W2b, (Vv*Hh)/4);

    // 1) gi = gather(emb) @ W_ih^T + b_ih  (fp32)
    {
        dim3 grid(G3/128, Mm/128);
        sgemm_kernel<<<grid, 256>>>(emb, W_ih, b_ih, p_gi, Mm, G3, Ee, inputs, 0);
    }

    // 2) GRU scan
    gru_persistent_kernel<<<GRU_BLOCKS, 256, gru_smem>>>(W_hh, b_hh);

    // 3) y = relu(hs @ W1^T + b1) -> bf16
    {
        dim3 grid(Hh/128, Mm/128);
        hmma_gemm_kernel<<<grid, 256, HG_SMEM>>>(p_hsb, p_W1b, b1, p_yb, Mm, Hh, Hh, 1, 1);
    }

    // 4) logits = y @ W2^T + b2 -> fp32 d_out
    //    PROBE: launched TWICE with identical args (idempotent rewrite of the
    //    same values). dur_us - 4394 measures the decoder GEMM time exactly.
    {
        dim3 grid(Vv/128, Mm/128);
        hmma_gemm_kernel<<<grid, 256, HG_SMEM>>>(p_yb, p_W2b, b2, out, Mm, Vv, Hh, 0, 0);
        hmma_gemm_kernel<<<grid, 256, HG_SMEM>>>(p_yb, p_W2b, b2, out, Mm, Vv, Hh, 0, 0);
    }

    // 5) fused log_softmax in place
    logsoftmax_kernel<<<Mm, 256, ls_smem>>>(out);

    // 6) hidden
    hidden_copy_kernel<<<(Bb*Hh)/256, 256>>>(out);
}

// round 10
// speedup vs baseline: 1.2839x; 1.2839x over previous
#include <cuda_runtime.h>
#include <cuda_bf16.h>
#include <math.h>
#include <cstdint>

#define Bb 16
#define Tt 256
#define Ee 512
#define Hh 1024
#define Vv 32000
#define G3 3072
#define Mm (Bb*Tt)   // 4096

#define GRU_BLOCKS 128
#define NPART 500            // (Vv/128)*2 partials per row
#define NPART_PAD 512

// ---- scratch ----
__device__ float g_gi[(size_t)Mm*G3];
__device__ float g_hs[(size_t)Mm*Hh];
__device__ float g_lse[Mm];
__device__ float2 g_part[(size_t)Mm*NPART_PAD];
__device__ __nv_bfloat16 g_W1b[(size_t)Hh*Hh];
__device__ __nv_bfloat16 g_W2b[(size_t)Vv*Hh];
__device__ __nv_bfloat16 g_hsb[(size_t)Mm*Hh];
__device__ __nv_bfloat16 g_yb [(size_t)Mm*Hh];
__device__ int g_flags[GRU_BLOCKS * 8];
__device__ int g_gen;

__device__ __forceinline__ uint32_t smem_u32(const void* p) {
    uint32_t a;
    asm("{ .reg .u64 t; cvta.to.shared.u64 t, %1; cvt.u32.u64 %0, t; }" : "=r"(a) : "l"(p));
    return a;
}
__device__ __forceinline__ void fma2(unsigned long long& d, unsigned long long a, unsigned long long b) {
    asm("fma.rn.f32x2 %0, %1, %2, %0;" : "+l"(d) : "l"(a), "l"(b));
}
__device__ __forceinline__ float sum2(unsigned long long v) {
    float lo, hi;
    asm("mov.b64 {%0, %1}, %2;" : "=f"(lo), "=f"(hi) : "l"(v));
    return lo + hi;
}

// ================= fp32 -> bf16 (weights only) =================
__global__ void f2bf_kernel(const float* __restrict__ x, __nv_bfloat16* __restrict__ o, int n4)
{
    int i = blockIdx.x * blockDim.x + threadIdx.x;
    if (i >= n4) return;
    float4 v = ((const float4*)x)[i];
    __nv_bfloat162* p = (__nv_bfloat162*)o + i * 2;
    p[0] = __floats2bfloat162_rn(v.x, v.y);
    p[1] = __floats2bfloat162_rn(v.z, v.w);
}

// ================= HMMA bf16 GEMM, 3-stage cp.async =================
// out_bf16=0 path additionally emits per-(row, 64-col) online-softmax partials.
#define HG_STRIDE  40
#define HG_ATILE   (128 * HG_STRIDE * 2)
#define HG_STAGE   (2 * HG_ATILE)
#define HG_NSTG    3
#define HG_SMEM    (HG_NSTG * HG_STAGE)

__device__ __forceinline__ void ldsm_x4(uint32_t* r, uint32_t addr) {
    asm volatile("ldmatrix.sync.aligned.m8n8.x4.shared.b16 {%0,%1,%2,%3}, [%4];"
                 : "=r"(r[0]), "=r"(r[1]), "=r"(r[2]), "=r"(r[3]) : "r"(addr));
}
__device__ __forceinline__ void mma16816(float* d, const uint32_t* a, uint32_t b0, uint32_t b1) {
    asm volatile("mma.sync.aligned.m16n8k16.row.col.f32.bf16.bf16.f32 "
                 "{%0,%1,%2,%3}, {%4,%5,%6,%7}, {%8,%9}, {%0,%1,%2,%3};"
                 : "+f"(d[0]), "+f"(d[1]), "+f"(d[2]), "+f"(d[3])
                 : "r"(a[0]), "r"(a[1]), "r"(a[2]), "r"(a[3]), "r"(b0), "r"(b1));
}
__device__ __forceinline__ void cp_async16(uint32_t saddr, const void* gaddr) {
    asm volatile("cp.async.cg.shared.global [%0], [%1], 16;" :: "r"(saddr), "l"(gaddr));
}

__global__ void __launch_bounds__(256) hmma_gemm_kernel(
    const __nv_bfloat16* __restrict__ A,
    const __nv_bfloat16* __restrict__ Bm,
    const float* __restrict__ bias,
    void* __restrict__ Cv,
    int M, int N, int K, int do_relu, int out_bf16)
{
    extern __shared__ char smem[];
    const uint32_t sb = smem_u32(smem);
    const int tid  = threadIdx.x;
    const int wid  = tid >> 5;
    const int lane = tid & 31;
    const int bn = blockIdx.x, bm = blockIdx.y;

    const int warp_m = wid & 3;
    const int warp_n = wid >> 2;

    float d[2][8][4];
#pragma unroll
    for (int i = 0; i < 2; i++)
#pragma unroll
        for (int j = 0; j < 8; j++)
#pragma unroll
            for (int q = 0; q < 4; q++) d[i][j][q] = 0.f;

    const int NK = K >> 5;
    const int lmat = lane >> 3;
    const int lrow = lane & 7;

    auto load_stage = [&](int it, int buf) {
        const int kt = it << 5;
        const uint32_t sa = sb + buf * HG_STAGE;
        const uint32_t sbB = sa + HG_ATILE;
#pragma unroll
        for (int s = 0; s < 2; s++) {
            const int idx = tid + s * 256;
            const int row = idx >> 2, c = idx & 3;
            cp_async16(sa + row * (HG_STRIDE*2) + c * 16,
                       A + (size_t)(bm * 128 + row) * K + kt + c * 8);
            cp_async16(sbB + row * (HG_STRIDE*2) + c * 16,
                       Bm + (size_t)(bn * 128 + row) * K + kt + c * 8);
        }
        asm volatile("cp.async.commit_group;");
    };

    load_stage(0, 0);
    load_stage(1, 1);

    for (int it = 0; it < NK; it++) {
        asm volatile("cp.async.wait_group 1;");
        __syncthreads();
        if (it + 2 < NK) load_stage(it + 2, (it + 2) % HG_NSTG);

        const uint32_t sa  = sb + (it % HG_NSTG) * HG_STAGE;
        const uint32_t sbB = sa + HG_ATILE;

#pragma unroll
        for (int ks = 0; ks < 2; ks++) {
            uint32_t a[2][4];
#pragma unroll
            for (int mt = 0; mt < 2; mt++) {
                const int row = warp_m * 32 + mt * 16 + (lmat & 1) * 8 + lrow;
                const int c   = ks * 2 + (lmat >> 1);
                ldsm_x4(a[mt], sa + row * (HG_STRIDE*2) + c * 16);
            }
            uint32_t b[4][4];
#pragma unroll
            for (int nt = 0; nt < 4; nt++) {
                const int n = warp_n * 64 + nt * 16 + (lmat >> 1) * 8 + lrow;
                const int c = ks * 2 + (lmat & 1);
                ldsm_x4(b[nt], sbB + n * (HG_STRIDE*2) + c * 16);
            }
#pragma unroll
            for (int mt = 0; mt < 2; mt++)
#pragma unroll
                for (int nt = 0; nt < 4; nt++) {
                    mma16816(d[mt][nt*2+0], a[mt], b[nt][0], b[nt][1]);
                    mma16816(d[mt][nt*2+1], a[mt], b[nt][2], b[nt][3]);
                }
        }
    }

    // ---- store epilogue ----
#pragma unroll
    for (int mt = 0; mt < 2; mt++) {
        const int row0 = bm * 128 + warp_m * 32 + mt * 16 + (lane >> 2);
#pragma unroll
        for (int nt8 = 0; nt8 < 8; nt8++) {
            const int col = bn * 128 + warp_n * 64 + nt8 * 8 + (lane & 3) * 2;
            const float b0 = bias[col], b1 = bias[col + 1];
            float2 v0, v1;
            v0.x = d[mt][nt8][0] + b0; v0.y = d[mt][nt8][1] + b1;
            v1.x = d[mt][nt8][2] + b0; v1.y = d[mt][nt8][3] + b1;
            if (do_relu) {
                v0.x = fmaxf(v0.x, 0.f); v0.y = fmaxf(v0.y, 0.f);
                v1.x = fmaxf(v1.x, 0.f); v1.y = fmaxf(v1.y, 0.f);
            }
            if (out_bf16) {
                __nv_bfloat162* C = (__nv_bfloat162*)Cv;
                C[((size_t)row0 * N + col) >> 1]       = __floats2bfloat162_rn(v0.x, v0.y);
                C[((size_t)(row0 + 8) * N + col) >> 1] = __floats2bfloat162_rn(v1.x, v1.y);
            } else {
                float* C = (float*)Cv;
                *(float2*)(C + (size_t)row0 * N + col)       = v0;
                *(float2*)(C + (size_t)(row0 + 8) * N + col) = v1;
            }
        }
    }

    // ---- fused online-softmax partials (decoder path only) ----
    if (!out_bf16) {
        const int colt = bn * 128 + warp_n * 64 + (lane & 3) * 2;
#pragma unroll
        for (int mt = 0; mt < 2; mt++) {
            const int rowb = bm * 128 + warp_m * 32 + mt * 16 + (lane >> 2);
#pragma unroll
            for (int half = 0; half < 2; half++) {
                float mx = -INFINITY;
#pragma unroll
                for (int nt8 = 0; nt8 < 8; nt8++) {
                    const float v0 = d[mt][nt8][half*2+0] + bias[colt + nt8*8];
                    const float v1 = d[mt][nt8][half*2+1] + bias[colt + nt8*8 + 1];
                    mx = fmaxf(mx, fmaxf(v0, v1));
                }
                float s = 0.f;
#pragma unroll
                for (int nt8 = 0; nt8 < 8; nt8++) {
                    const float v0 = d[mt][nt8][half*2+0] + bias[colt + nt8*8];
                    const float v1 = d[mt][nt8][half*2+1] + bias[colt + nt8*8 + 1];
                    s += __expf(v0 - mx) + __expf(v1 - mx);
                }
#pragma unroll
                for (int o = 1; o <= 2; o <<= 1) {
                    const float m2 = __shfl_xor_sync(0xffffffffu, mx, o);
                    const float s2 = __shfl_xor_sync(0xffffffffu, s, o);
                    const float M_ = fmaxf(mx, m2);
                    s = s * __expf(mx - M_) + s2 * __expf(m2 - M_);
                    mx = M_;
                }
                if ((lane & 3) == 0) {
                    const int row = rowb + half * 8;
                    g_part[(size_t)row * NPART_PAD + bn * 2 + warp_n] = make_float2(mx, s);
                }
            }
        }
    }
}

// ================= fp32 SIMT SGEMM (gi, gathered A) =================
__global__ void sgemm_kernel(const float* __restrict__ A,
                             const float* __restrict__ Bm,
                             const float* __restrict__ bias,
                             float* __restrict__ C,
                             int M, int N, int K,
                             const int* __restrict__ gidx,
                             int do_relu)
{
    __shared__ float As[8][128];
    __shared__ float Bs[8][128];

    const int tid = threadIdx.x;
    const int bn  = blockIdx.x;
    const int bm  = blockIdx.y;

    const int lrow = tid >> 1;
    const int kq   = (tid & 1) * 4;

    const int arow_g = bm * 128 + lrow;
    const float* Ap = gidx ? (A + (size_t)gidx[arow_g] * K)
                           : (A + (size_t)arow_g * K);
    const float* Bp = Bm + (size_t)(bn * 128 + lrow) * K;

    const int tx = tid & 15;
    const int ty = tid >> 4;
    const int m0 = ty * 8;
    const int n0 = tx * 8;

    float acc[8][8];
#pragma unroll
    for (int i = 0; i < 8; i++)
#pragma unroll
        for (int j = 0; j < 8; j++) acc[i][j] = 0.f;

    for (int kt = 0; kt < K; kt += 8) {
        float4 av = *(const float4*)(Ap + kt + kq);
        float4 bv = *(const float4*)(Bp + kt + kq);
        As[kq+0][lrow] = av.x; As[kq+1][lrow] = av.y;
        As[kq+2][lrow] = av.z; As[kq+3][lrow] = av.w;
        Bs[kq+0][lrow] = bv.x; Bs[kq+1][lrow] = bv.y;
        Bs[kq+2][lrow] = bv.z; Bs[kq+3][lrow] = bv.w;
        __syncthreads();

#pragma unroll
        for (int kk = 0; kk < 8; kk++) {
            float4 a0 = *(const float4*)&As[kk][m0];
            float4 a1 = *(const float4*)&As[kk][m0 + 4];
            float4 b0 = *(const float4*)&Bs[kk][n0];
            float4 b1 = *(const float4*)&Bs[kk][n0 + 4];
            float am[8] = {a0.x,a0.y,a0.z,a0.w,a1.x,a1.y,a1.z,a1.w};
            float bb[8] = {b0.x,b0.y,b0.z,b0.w,b1.x,b1.y,b1.z,b1.w};
#pragma unroll
            for (int i = 0; i < 8; i++)
#pragma unroll
                for (int j = 0; j < 8; j++)
                    acc[i][j] = fmaf(am[i], bb[j], acc[i][j]);
        }
        __syncthreads();
    }

    const int ncol0 = bn * 128 + n0;
    float bsv[8];
#pragma unroll
    for (int j = 0; j < 8; j++) bsv[j] = bias[ncol0 + j];

#pragma unroll
    for (int i = 0; i < 8; i++) {
        const int m = bm * 128 + m0 + i;
        float* crow = C + (size_t)m * N + ncol0;
#pragma unroll
        for (int jq = 0; jq < 2; jq++) {
            float4 v;
            v.x = acc[i][jq*4+0] + bsv[jq*4+0];
            v.y = acc[i][jq*4+1] + bsv[jq*4+1];
            v.z = acc[i][jq*4+2] + bsv[jq*4+2];
            v.w = acc[i][jq*4+3] + bsv[jq*4+3];
            if (do_relu) {
                v.x = fmaxf(v.x, 0.f); v.y = fmaxf(v.y, 0.f);
                v.z = fmaxf(v.z, 0.f); v.w = fmaxf(v.w, 0.f);
            }
            *(float4*)(crow + jq*4) = v;
        }
    }
}

// ================= persistent GRU, flag-based grid barrier =================
__global__ void __launch_bounds__(256) gru_persistent_kernel(
    const float* __restrict__ W_hh,
    const float* __restrict__ b_hh)
{
    extern __shared__ float smf[];
    float* W_s = smf;
    float* h_s = smf + 24*1024;

    const int tid  = threadIdx.x;
    const int w    = tid >> 5;
    const int lane = tid & 31;
    const int blk  = blockIdx.x;
    const int j    = blk * 8 + w;

    for (int idx = tid; idx < 24 * 256; idx += 256) {
        const int r = idx >> 8;
        const int q = idx & 255;
        const int g = r >> 3, wr = r & 7;
        *(float4*)&W_s[r*1024 + q*4] =
            *(const float4*)&W_hh[((size_t)(g*Hh + blk*8 + wr))*Hh + q*4];
    }
    for (int i = tid; i < Bb*Hh/4; i += 256)
        ((float4*)h_s)[i] = make_float4(0.f,0.f,0.f,0.f);
    __syncthreads();

    const float* wr_s = W_s + (0*8 + w) * 1024;
    const float* wz_s = W_s + (1*8 + w) * 1024;
    const float* wn_s = W_s + (2*8 + w) * 1024;
    const float bhr = b_hh[j], bhz = b_hh[j + Hh], bhn = b_hh[j + 2*Hh];

    for (int t = 0; t < Tt; t++) {
        float ir = 0.f, iz = 0.f, inn = 0.f;
        if (lane < 16) {
            const float* gi = g_gi + ((size_t)(lane*Tt + t)) * G3;
            ir  = __ldcg(gi + j);
            iz  = __ldcg(gi + j + Hh);
            inn = __ldcg(gi + j + 2*Hh);
        }

        unsigned long long ar2[16], az2[16], an2[16];
#pragma unroll
        for (int b = 0; b < 16; b++) { ar2[b] = 0ull; az2[b] = 0ull; an2[b] = 0ull; }

#pragma unroll 2
        for (int i = 0; i < 16; i++) {
            const int k2 = i*64 + lane*2;
            const unsigned long long vr = *(const unsigned long long*)&wr_s[k2];
            const unsigned long long vz = *(const unsigned long long*)&wz_s[k2];
            const unsigned long long vn = *(const unsigned long long*)&wn_s[k2];
#pragma unroll
            for (int b = 0; b < 16; b++) {
                const unsigned long long hv = *(const unsigned long long*)&h_s[b*Hh + k2];
                fma2(ar2[b], vr, hv);
                fma2(az2[b], vz, hv);
                fma2(an2[b], vn, hv);
            }
        }

        float ar[16], az[16], an[16];
#pragma unroll
        for (int b = 0; b < 16; b++) {
            ar[b] = sum2(ar2[b]);
            az[b] = sum2(az2[b]);
            an[b] = sum2(an2[b]);
        }

#pragma unroll
        for (int b = 0; b < 16; b++) {
#pragma unroll
            for (int o = 16; o > 0; o >>= 1) {
                ar[b] += __shfl_xor_sync(0xffffffffu, ar[b], o);
                az[b] += __shfl_xor_sync(0xffffffffu, az[b], o);
                an[b] += __shfl_xor_sync(0xffffffffu, an[b], o);
            }
        }

        if (lane < 16) {
            const int b = lane;
            const float r = 1.f / (1.f + expf(-(ir + ar[b] + bhr)));
            const float z = 1.f / (1.f + expf(-(iz + az[b] + bhz)));
            const float n = tanhf(inn + r * (an[b] + bhn));
            const float hp = h_s[b*Hh + j];
            const float h_new = (1.f - z)*n + z*hp;
            g_hs[((size_t)(b*Tt + t))*Hh + j] = h_new;
            g_hsb[((size_t)(b*Tt + t))*Hh + j] = __float2bfloat16(h_new);
        }

        if (t + 1 < Tt) {
            __syncthreads();
            if (tid == 0) {
                __threadfence();
                *(volatile int*)&g_flags[blk * 8] = t + 1;
            }
            if (blk == 0) {
                if (tid < GRU_BLOCKS) {
                    while (*(volatile int*)&g_flags[tid * 8] < t + 1) __nanosleep(32);
                }
                __syncthreads();
                if (tid == 0) { __threadfence(); *(volatile int*)&g_gen = t + 1; }
            } else {
                if (tid == 0) {
                    while (*(volatile int*)&g_gen < t + 1) __nanosleep(32);
                    __threadfence();
                }
                __syncthreads();
            }
            for (int i = tid*4; i < Bb*Hh; i += 256*4) {
                const int b = i >> 10;
                const int k = i & (Hh-1);
                *(float4*)&h_s[i] =
                    __ldcg((const float4*)&g_hs[((size_t)(b*Tt + t))*Hh + k]);
            }
            __syncthreads();
        }
    }

    __syncthreads();
    if (tid == 0) { __threadfence(); *(volatile int*)&g_flags[blk * 8] = 0; }
    if (blk == 0) {
        if (tid < GRU_BLOCKS) {
            while (*(volatile int*)&g_flags[tid * 8] != 0) __nanosleep(32);
        }
        __syncthreads();
        if (tid == 0) *(volatile int*)&g_gen = 0;
    }
}

// ================= lse reduce (combine per-row partials) =================
__global__ void __launch_bounds__(256) lse_reduce_kernel()
{
    const int row = blockIdx.x;
    const int tid = threadIdx.x;
    float m = -INFINITY, s = 0.f;
    for (int i = tid; i < NPART; i += 256) {
        const float2 p = g_part[(size_t)row * NPART_PAD + i];
        const float M_ = fmaxf(m, p.x);
        s = s * __expf(m - M_) + p.y * __expf(p.x - M_);
        m = M_;
    }
    __shared__ float sm[256], ss[256];
    sm[tid] = m; ss[tid] = s;
    __syncthreads();
    for (int o = 128; o > 0; o >>= 1) {
        if (tid < o) {
            const float m2 = sm[tid + o], s2 = ss[tid + o];
            const float M_ = fmaxf(sm[tid], m2);
            ss[tid] = ss[tid]*__expf(sm[tid]-M_) + s2*__expf(m2-M_);
            sm[tid] = M_;
        }
        __syncthreads();
    }
    if (tid == 0) g_lse[row] = sm[0] + logf(ss[0]);
}

// ================= subtract lse (exp-free streaming pass) =================
__global__ void sub_kernel(float* __restrict__ out)
{
    const size_t i = (size_t)blockIdx.x * blockDim.x + threadIdx.x;
    const size_t n4 = (size_t)Mm * Vv / 4;
    if (i >= n4) return;
    const int row = (int)((i * 4) / Vv);
    const float l = g_lse[row];
    float4 v = ((float4*)out)[i];
    v.x -= l; v.y -= l; v.z -= l; v.w -= l;
    ((float4*)out)[i] = v;
}

__global__ void hidden_copy_kernel(float* __restrict__ out)
{
    const int i = blockIdx.x * blockDim.x + threadIdx.x;
    const int b = i >> 10;
    const int j = i & (Hh - 1);
    out[(size_t)Mm*Vv + i] = g_hs[((size_t)(b*Tt + Tt - 1))*Hh + j];
}

// ============================================================
extern "C" void kernel_launch(void* const* d_in, const int* in_sizes, int n_in,
                              void* d_out, int out_size)
{
    const int*   inputs = (const int*)  d_in[0];
    const float* emb    = (const float*)d_in[1];
    const float* W_ih   = (const float*)d_in[2];
    const float* W_hh   = (const float*)d_in[3];
    const float* b_ih   = (const float*)d_in[4];
    const float* b_hh   = (const float*)d_in[5];
    const float* W1     = (const float*)d_in[6];
    const float* b1     = (const float*)d_in[7];
    const float* W2     = (const float*)d_in[8];
    const float* b2     = (const float*)d_in[9];
    float* out = (float*)d_out;

    float *p_gi;
    __nv_bfloat16 *p_W1b, *p_W2b, *p_hsb, *p_yb;
    cudaGetSymbolAddress((void**)&p_gi,  g_gi);
    cudaGetSymbolAddress((void**)&p_W1b, g_W1b);
    cudaGetSymbolAddress((void**)&p_W2b, g_W2b);
    cudaGetSymbolAddress((void**)&p_hsb, g_hsb);
    cudaGetSymbolAddress((void**)&p_yb,  g_yb);

    const int gru_smem = (24*1024 + 16*1024) * 4;
    cudaFuncSetAttribute(gru_persistent_kernel,
                         cudaFuncAttributeMaxDynamicSharedMemorySize, gru_smem);
    cudaFuncSetAttribute(hmma_gemm_kernel,
                         cudaFuncAttributeMaxDynamicSharedMemorySize, HG_SMEM);

    // 0) weight -> bf16
    f2bf_kernel<<<(Hh*Hh)/1024, 256>>>(W1, p_W1b, (Hh*Hh)/4);
    f2bf_kernel<<<((size_t)Vv*Hh)/1024, 256>>>(W2, p_W2b, (Vv*Hh)/4);

    // 1) gi = gather(emb) @ W_ih^T + b_ih  (fp32)
    {
        dim3 grid(G3/128, Mm/128);
        sgemm_kernel<<<grid, 256>>>(emb, W_ih, b_ih, p_gi, Mm, G3, Ee, inputs, 0);
    }

    // 2) GRU scan
    gru_persistent_kernel<<<GRU_BLOCKS, 256, gru_smem>>>(W_hh, b_hh);

    // 3) y = relu(hs @ W1^T + b1) -> bf16
    {
        dim3 grid(Hh/128, Mm/128);
        hmma_gemm_kernel<<<grid, 256, HG_SMEM>>>(p_hsb, p_W1b, b1, p_yb, Mm, Hh, Hh, 1, 1);
    }

    // 4) logits = y @ W2^T + b2 -> fp32 d_out, WITH fused softmax partials
    {
        dim3 grid(Vv/128, Mm/128);
        hmma_gemm_kernel<<<grid, 256, HG_SMEM>>>(p_yb, p_W2b, b2, out, Mm, Vv, Hh, 0, 0);
    }

    // 5) lse = combine partials; then exp-free subtract
    lse_reduce_kernel<<<Mm, 256>>>();
    {
        const size_t n4 = (size_t)Mm * Vv / 4;
        sub_kernel<<<(int)((n4 + 255) / 256), 256>>>(out);
    }

    // 6) hidden
    hidden_copy_kernel<<<(Bb*Hh)/256, 256>>>(out);
}

// round 12
// speedup vs baseline: 1.3760x; 1.0717x over previous
#include <cuda_runtime.h>
#include <cuda_bf16.h>
#include <math.h>
#include <cstdint>

#define Bb 16
#define Tt 256
#define Ee 512
#define Hh 1024
#define Vv 32000
#define G3 3072
#define Mm (Bb*Tt)   // 4096

#define GRU_BLOCKS 128
#define GRU_THREADS 512
#define NPART 500
#define NPART_PAD 512

// ---- scratch ----
__device__ float g_gi[(size_t)Mm*G3];
__device__ float g_hs[(size_t)Mm*Hh];
__device__ float g_lse[Mm];
__device__ float2 g_part[(size_t)Mm*NPART_PAD];
__device__ __nv_bfloat16 g_W1b[(size_t)Hh*Hh];
__device__ __nv_bfloat16 g_W2b[(size_t)Vv*Hh];
__device__ __nv_bfloat16 g_hsb[(size_t)Mm*Hh];
__device__ __nv_bfloat16 g_yb [(size_t)Mm*Hh];
__device__ int g_flags[GRU_BLOCKS * 8];   // 32B-padded per-block flags

__device__ __forceinline__ uint32_t smem_u32(const void* p) {
    uint32_t a;
    asm("{ .reg .u64 t; cvta.to.shared.u64 t, %1; cvt.u32.u64 %0, t; }" : "=r"(a) : "l"(p));
    return a;
}
__device__ __forceinline__ void fma2(unsigned long long& d, unsigned long long a, unsigned long long b) {
    asm("fma.rn.f32x2 %0, %1, %2, %0;" : "+l"(d) : "l"(a), "l"(b));
}
__device__ __forceinline__ float sum2(unsigned long long v) {
    float lo, hi;
    asm("mov.b64 {%0, %1}, %2;" : "=f"(lo), "=f"(hi) : "l"(v));
    return lo + hi;
}
__device__ __forceinline__ unsigned long long pack2(float lo, float hi) {
    unsigned long long v;
    asm("mov.b64 %0, {%1, %2};" : "=l"(v) : "f"(lo), "f"(hi));
    return v;
}

// ================= fp32 -> bf16 (weights only) =================
__global__ void f2bf_kernel(const float* __restrict__ x, __nv_bfloat16* __restrict__ o, int n4)
{
    int i = blockIdx.x * blockDim.x + threadIdx.x;
    if (i >= n4) return;
    float4 v = ((const float4*)x)[i];
    __nv_bfloat162* p = (__nv_bfloat162*)o + i * 2;
    p[0] = __floats2bfloat162_rn(v.x, v.y);
    p[1] = __floats2bfloat162_rn(v.z, v.w);
}

// ================= HMMA bf16 GEMM, 3-stage cp.async (+fused softmax partials) =================
#define HG_STRIDE  40
#define HG_ATILE   (128 * HG_STRIDE * 2)
#define HG_STAGE   (2 * HG_ATILE)
#define HG_NSTG    3
#define HG_SMEM    (HG_NSTG * HG_STAGE)

__device__ __forceinline__ void ldsm_x4(uint32_t* r, uint32_t addr) {
    asm volatile("ldmatrix.sync.aligned.m8n8.x4.shared.b16 {%0,%1,%2,%3}, [%4];"
                 : "=r"(r[0]), "=r"(r[1]), "=r"(r[2]), "=r"(r[3]) : "r"(addr));
}
__device__ __forceinline__ void mma16816(float* d, const uint32_t* a, uint32_t b0, uint32_t b1) {
    asm volatile("mma.sync.aligned.m16n8k16.row.col.f32.bf16.bf16.f32 "
                 "{%0,%1,%2,%3}, {%4,%5,%6,%7}, {%8,%9}, {%0,%1,%2,%3};"
                 : "+f"(d[0]), "+f"(d[1]), "+f"(d[2]), "+f"(d[3])
                 : "r"(a[0]), "r"(a[1]), "r"(a[2]), "r"(a[3]), "r"(b0), "r"(b1));
}
__device__ __forceinline__ void cp_async16(uint32_t saddr, const void* gaddr) {
    asm volatile("cp.async.cg.shared.global [%0], [%1], 16;" :: "r"(saddr), "l"(gaddr));
}

__global__ void __launch_bounds__(256) hmma_gemm_kernel(
    const __nv_bfloat16* __restrict__ A,
    const __nv_bfloat16* __restrict__ Bm,
    const float* __restrict__ bias,
    void* __restrict__ Cv,
    int M, int N, int K, int do_relu, int out_bf16)
{
    extern __shared__ char smem[];
    const uint32_t sb = smem_u32(smem);
    const int tid  = threadIdx.x;
    const int wid  = tid >> 5;
    const int lane = tid & 31;
    const int bn = blockIdx.x, bm = blockIdx.y;

    const int warp_m = wid & 3;
    const int warp_n = wid >> 2;

    float d[2][8][4];
#pragma unroll
    for (int i = 0; i < 2; i++)
#pragma unroll
        for (int j = 0; j < 8; j++)
#pragma unroll
            for (int q = 0; q < 4; q++) d[i][j][q] = 0.f;

    const int NK = K >> 5;
    const int lmat = lane >> 3;
    const int lrow = lane & 7;

    auto load_stage = [&](int it, int buf) {
        const int kt = it << 5;
        const uint32_t sa = sb + buf * HG_STAGE;
        const uint32_t sbB = sa + HG_ATILE;
#pragma unroll
        for (int s = 0; s < 2; s++) {
            const int idx = tid + s * 256;
            const int row = idx >> 2, c = idx & 3;
            cp_async16(sa + row * (HG_STRIDE*2) + c * 16,
                       A + (size_t)(bm * 128 + row) * K + kt + c * 8);
            cp_async16(sbB + row * (HG_STRIDE*2) + c * 16,
                       Bm + (size_t)(bn * 128 + row) * K + kt + c * 8);
        }
        asm volatile("cp.async.commit_group;");
    };

    load_stage(0, 0);
    load_stage(1, 1);

    for (int it = 0; it < NK; it++) {
        asm volatile("cp.async.wait_group 1;");
        __syncthreads();
        if (it + 2 < NK) load_stage(it + 2, (it + 2) % HG_NSTG);

        const uint32_t sa  = sb + (it % HG_NSTG) * HG_STAGE;
        const uint32_t sbB = sa + HG_ATILE;

#pragma unroll
        for (int ks = 0; ks < 2; ks++) {
            uint32_t a[2][4];
#pragma unroll
            for (int mt = 0; mt < 2; mt++) {
                const int row = warp_m * 32 + mt * 16 + (lmat & 1) * 8 + lrow;
                const int c   = ks * 2 + (lmat >> 1);
                ldsm_x4(a[mt], sa + row * (HG_STRIDE*2) + c * 16);
            }
            uint32_t b[4][4];
#pragma unroll
            for (int nt = 0; nt < 4; nt++) {
                const int n = warp_n * 64 + nt * 16 + (lmat >> 1) * 8 + lrow;
                const int c = ks * 2 + (lmat & 1);
                ldsm_x4(b[nt], sbB + n * (HG_STRIDE*2) + c * 16);
            }
#pragma unroll
            for (int mt = 0; mt < 2; mt++)
#pragma unroll
                for (int nt = 0; nt < 4; nt++) {
                    mma16816(d[mt][nt*2+0], a[mt], b[nt][0], b[nt][1]);
                    mma16816(d[mt][nt*2+1], a[mt], b[nt][2], b[nt][3]);
                }
        }
    }

#pragma unroll
    for (int mt = 0; mt < 2; mt++) {
        const int row0 = bm * 128 + warp_m * 32 + mt * 16 + (lane >> 2);
#pragma unroll
        for (int nt8 = 0; nt8 < 8; nt8++) {
            const int col = bn * 128 + warp_n * 64 + nt8 * 8 + (lane & 3) * 2;
            const float b0 = bias[col], b1 = bias[col + 1];
            float2 v0, v1;
            v0.x = d[mt][nt8][0] + b0; v0.y = d[mt][nt8][1] + b1;
            v1.x = d[mt][nt8][2] + b0; v1.y = d[mt][nt8][3] + b1;
            if (do_relu) {
                v0.x = fmaxf(v0.x, 0.f); v0.y = fmaxf(v0.y, 0.f);
                v1.x = fmaxf(v1.x, 0.f); v1.y = fmaxf(v1.y, 0.f);
            }
            if (out_bf16) {
                __nv_bfloat162* C = (__nv_bfloat162*)Cv;
                C[((size_t)row0 * N + col) >> 1]       = __floats2bfloat162_rn(v0.x, v0.y);
                C[((size_t)(row0 + 8) * N + col) >> 1] = __floats2bfloat162_rn(v1.x, v1.y);
            } else {
                float* C = (float*)Cv;
                *(float2*)(C + (size_t)row0 * N + col)       = v0;
                *(float2*)(C + (size_t)(row0 + 8) * N + col) = v1;
            }
        }
    }

    if (!out_bf16) {
        const int colt = bn * 128 + warp_n * 64 + (lane & 3) * 2;
#pragma unroll
        for (int mt = 0; mt < 2; mt++) {
            const int rowb = bm * 128 + warp_m * 32 + mt * 16 + (lane >> 2);
#pragma unroll
            for (int half = 0; half < 2; half++) {
                float mx = -INFINITY;
#pragma unroll
                for (int nt8 = 0; nt8 < 8; nt8++) {
                    const float v0 = d[mt][nt8][half*2+0] + bias[colt + nt8*8];
                    const float v1 = d[mt][nt8][half*2+1] + bias[colt + nt8*8 + 1];
                    mx = fmaxf(mx, fmaxf(v0, v1));
                }
                float s = 0.f;
#pragma unroll
                for (int nt8 = 0; nt8 < 8; nt8++) {
                    const float v0 = d[mt][nt8][half*2+0] + bias[colt + nt8*8];
                    const float v1 = d[mt][nt8][half*2+1] + bias[colt + nt8*8 + 1];
                    s += __expf(v0 - mx) + __expf(v1 - mx);
                }
#pragma unroll
                for (int o = 1; o <= 2; o <<= 1) {
                    const float m2 = __shfl_xor_sync(0xffffffffu, mx, o);
                    const float s2 = __shfl_xor_sync(0xffffffffu, s, o);
                    const float M_ = fmaxf(mx, m2);
                    s = s * __expf(mx - M_) + s2 * __expf(m2 - M_);
                    mx = M_;
                }
                if ((lane & 3) == 0) {
                    const int row = rowb + half * 8;
                    g_part[(size_t)row * NPART_PAD + bn * 2 + warp_n] = make_float2(mx, s);
                }
            }
        }
    }
}

// ================= fp32 SIMT SGEMM (gi, gathered A) =================
__global__ void sgemm_kernel(const float* __restrict__ A,
                             const float* __restrict__ Bm,
                             const float* __restrict__ bias,
                             float* __restrict__ C,
                             int M, int N, int K,
                             const int* __restrict__ gidx,
                             int do_relu)
{
    __shared__ float As[8][128];
    __shared__ float Bs[8][128];

    const int tid = threadIdx.x;
    const int bn  = blockIdx.x;
    const int bm  = blockIdx.y;

    const int lrow = tid >> 1;
    const int kq   = (tid & 1) * 4;

    const int arow_g = bm * 128 + lrow;
    const float* Ap = gidx ? (A + (size_t)gidx[arow_g] * K)
                           : (A + (size_t)arow_g * K);
    const float* Bp = Bm + (size_t)(bn * 128 + lrow) * K;

    const int tx = tid & 15;
    const int ty = tid >> 4;
    const int m0 = ty * 8;
    const int n0 = tx * 8;

    float acc[8][8];
#pragma unroll
    for (int i = 0; i < 8; i++)
#pragma unroll
        for (int j = 0; j < 8; j++) acc[i][j] = 0.f;

    for (int kt = 0; kt < K; kt += 8) {
        float4 av = *(const float4*)(Ap + kt + kq);
        float4 bv = *(const float4*)(Bp + kt + kq);
        As[kq+0][lrow] = av.x; As[kq+1][lrow] = av.y;
        As[kq+2][lrow] = av.z; As[kq+3][lrow] = av.w;
        Bs[kq+0][lrow] = bv.x; Bs[kq+1][lrow] = bv.y;
        Bs[kq+2][lrow] = bv.z; Bs[kq+3][lrow] = bv.w;
        __syncthreads();

#pragma unroll
        for (int kk = 0; kk < 8; kk++) {
            float4 a0 = *(const float4*)&As[kk][m0];
            float4 a1 = *(const float4*)&As[kk][m0 + 4];
            float4 b0 = *(const float4*)&Bs[kk][n0];
            float4 b1 = *(const float4*)&Bs[kk][n0 + 4];
            float am[8] = {a0.x,a0.y,a0.z,a0.w,a1.x,a1.y,a1.z,a1.w};
            float bb[8] = {b0.x,b0.y,b0.z,b0.w,b1.x,b1.y,b1.z,b1.w};
#pragma unroll
            for (int i = 0; i < 8; i++)
#pragma unroll
                for (int j = 0; j < 8; j++)
                    acc[i][j] = fmaf(am[i], bb[j], acc[i][j]);
        }
        __syncthreads();
    }

    const int ncol0 = bn * 128 + n0;
    float bsv[8];
#pragma unroll
    for (int j = 0; j < 8; j++) bsv[j] = bias[ncol0 + j];

#pragma unroll
    for (int i = 0; i < 8; i++) {
        const int m = bm * 128 + m0 + i;
        float* crow = C + (size_t)m * N + ncol0;
#pragma unroll
        for (int jq = 0; jq < 2; jq++) {
            float4 v;
            v.x = acc[i][jq*4+0] + bsv[jq*4+0];
            v.y = acc[i][jq*4+1] + bsv[jq*4+1];
            v.z = acc[i][jq*4+2] + bsv[jq*4+2];
            v.w = acc[i][jq*4+3] + bsv[jq*4+3];
            if (do_relu) {
                v.x = fmaxf(v.x, 0.f); v.y = fmaxf(v.y, 0.f);
                v.z = fmaxf(v.z, 0.f); v.w = fmaxf(v.w, 0.f);
            }
            *(float4*)(crow + jq*4) = v;
        }
    }
}

// ================= GRU v2: 512 threads, b-in-lane, k-split =================
// smem: W_s[24][1024] | hT[512 k-pairs][16 b][2] pad 34 | cmb[8][3][16]
#define HT_PAD    34
#define HT_FLOATS (512*HT_PAD)
#define GRU_SMEM  ((24*1024 + HT_FLOATS + 8*3*16) * 4)

__global__ void gru_reset_kernel()
{
    g_flags[threadIdx.x * 8] = 0;
}

__global__ void __launch_bounds__(GRU_THREADS) gru_persistent_kernel(
    const float* __restrict__ W_hh,
    const float* __restrict__ b_hh)
{
    extern __shared__ float smf[];
    float* W_s = smf;                       // 24*1024
    float* hT  = smf + 24*1024;             // 512*34
    float* cmb = hT + HT_FLOATS;            // 8*3*16

    const int tid  = threadIdx.x;
    const int wid  = tid >> 5;              // 0..15
    const int lane = tid & 31;
    const int blk  = blockIdx.x;
    const int jj   = wid & 7;
    const int kh   = wid >> 3;              // 0/1
    const int j    = blk * 8 + jj;
    const int b    = lane & 15;
    const int ks   = lane >> 4;             // 0/1
    const int k0   = kh * 512 + ks * 256;

    // load W slice
    for (int idx = tid; idx < 24*256; idx += GRU_THREADS) {
        const int r = idx >> 8;
        const int q = idx & 255;
        const int gate = r >> 3, wr = r & 7;
        *(float4*)&W_s[r*1024 + q*4] =
            *(const float4*)&W_hh[((size_t)(gate*Hh + blk*8 + wr))*Hh + q*4];
    }
    for (int i = tid; i < HT_FLOATS; i += GRU_THREADS) hT[i] = 0.f;
    __syncthreads();

    const float* wr_s = W_s + (0*8 + jj) * 1024;
    const float* wz_s = W_s + (1*8 + jj) * 1024;
    const float* wn_s = W_s + (2*8 + jj) * 1024;

    float bhr = 0.f, bhz = 0.f, bhn = 0.f;
    if (kh == 0 && lane < 16) {
        bhr = b_hh[j]; bhz = b_hh[j + Hh]; bhn = b_hh[j + 2*Hh];
    }

    for (int t = 0; t < Tt; t++) {
        // gi prefetch (only the threads that do gate math)
        float ir = 0.f, iz = 0.f, inn = 0.f;
        if (kh == 0 && lane < 16) {
            const float* gi = g_gi + ((size_t)(b*Tt + t)) * G3;
            ir  = __ldcg(gi + j);
            iz  = __ldcg(gi + j + Hh);
            inn = __ldcg(gi + j + 2*Hh);
        }

        // main dot-product: 256 k per thread, 4 k per iteration
        unsigned long long accr = 0ull, accz = 0ull, accn = 0ull;
        const float* hrow = hT + b*2;
#pragma unroll 8
        for (int kk = 0; kk < 256; kk += 4) {
            const int k = k0 + kk;
            const float4 wr4 = *(const float4*)&wr_s[k];
            const float4 wz4 = *(const float4*)&wz_s[k];
            const float4 wn4 = *(const float4*)&wn_s[k];
            const unsigned long long h01 = *(const unsigned long long*)&hrow[(k>>1)*HT_PAD];
            const unsigned long long h23 = *(const unsigned long long*)&hrow[((k>>1)+1)*HT_PAD];
            fma2(accr, pack2(wr4.x, wr4.y), h01);
            fma2(accz, pack2(wz4.x, wz4.y), h01);
            fma2(accn, pack2(wn4.x, wn4.y), h01);
            fma2(accr, pack2(wr4.z, wr4.w), h23);
            fma2(accz, pack2(wz4.z, wz4.w), h23);
            fma2(accn, pack2(wn4.z, wn4.w), h23);
        }
        float sr = sum2(accr), sz = sum2(accz), sn = sum2(accn);
        // reduce across ks (lane ^ 16)
        sr += __shfl_xor_sync(0xffffffffu, sr, 16);
        sz += __shfl_xor_sync(0xffffffffu, sz, 16);
        sn += __shfl_xor_sync(0xffffffffu, sn, 16);

        // cross-kh combine via smem
        if (kh == 1 && lane < 16) {
            cmb[(jj*3 + 0)*16 + b] = sr;
            cmb[(jj*3 + 1)*16 + b] = sz;
            cmb[(jj*3 + 2)*16 + b] = sn;
        }
        __syncthreads();

        if (kh == 0 && lane < 16) {
            sr += cmb[(jj*3 + 0)*16 + b];
            sz += cmb[(jj*3 + 1)*16 + b];
            sn += cmb[(jj*3 + 2)*16 + b];
            const float r = 1.f / (1.f + expf(-(ir + sr + bhr)));
            const float z = 1.f / (1.f + expf(-(iz + sz + bhz)));
            const float n = tanhf(inn + r * (sn + bhn));
            const float hp = hT[(j>>1)*HT_PAD + b*2 + (j&1)];
            const float h_new = (1.f - z)*n + z*hp;
            g_hs [((size_t)(b*Tt + t))*Hh + j] = h_new;
            g_hsb[((size_t)(b*Tt + t))*Hh + j] = __float2bfloat16(h_new);
        }

        if (t + 1 < Tt) {
            __syncthreads();
            if (tid == 0) {
                __threadfence();
                *(volatile int*)&g_flags[blk * 8] = t + 1;
            }
            if (tid < GRU_BLOCKS) {
                while (*(volatile int*)&g_flags[tid * 8] < t + 1) __nanosleep(32);
                __threadfence();
            }
            __syncthreads();
            // restage transposed: warp = batch (wid), lanes = j4 chunks
            const float* src = &g_hs[((size_t)(wid*Tt + t))*Hh];
#pragma unroll
            for (int it = 0; it < 8; it++) {
                const int j4 = lane + it*32;            // float4 index
                const float4 v = __ldcg((const float4*)src + j4);
                *(float2*)&hT[(j4*2)*HT_PAD   + wid*2] = make_float2(v.x, v.y);
                *(float2*)&hT[(j4*2+1)*HT_PAD + wid*2] = make_float2(v.z, v.w);
            }
            __syncthreads();
        }
    }
}

// ================= lse reduce + subtract =================
__global__ void __launch_bounds__(256) lse_reduce_kernel()
{
    const int row = blockIdx.x;
    const int tid = threadIdx.x;
    float m = -INFINITY, s = 0.f;
    for (int i = tid; i < NPART; i += 256) {
        const float2 p = g_part[(size_t)row * NPART_PAD + i];
        const float M_ = fmaxf(m, p.x);
        s = s * __expf(m - M_) + p.y * __expf(p.x - M_);
        m = M_;
    }
    __shared__ float sm[256], ss[256];
    sm[tid] = m; ss[tid] = s;
    __syncthreads();
    for (int o = 128; o > 0; o >>= 1) {
        if (tid < o) {
            const float m2 = sm[tid + o], s2 = ss[tid + o];
            const float M_ = fmaxf(sm[tid], m2);
            ss[tid] = ss[tid]*__expf(sm[tid]-M_) + s2*__expf(m2-M_);
            sm[tid] = M_;
        }
        __syncthreads();
    }
    if (tid == 0) g_lse[row] = sm[0] + logf(ss[0]);
}

__global__ void sub_kernel(float* __restrict__ out)
{
    const size_t i = (size_t)blockIdx.x * blockDim.x + threadIdx.x;
    const size_t n4 = (size_t)Mm * Vv / 4;
    if (i >= n4) return;
    const int row = (int)((i * 4) / Vv);
    const float l = g_lse[row];
    float4 v = ((float4*)out)[i];
    v.x -= l; v.y -= l; v.z -= l; v.w -= l;
    ((float4*)out)[i] = v;
}

__global__ void hidden_copy_kernel(float* __restrict__ out)
{
    const int i = blockIdx.x * blockDim.x + threadIdx.x;
    const int b = i >> 10;
    const int j = i & (Hh - 1);
    out[(size_t)Mm*Vv + i] = g_hs[((size_t)(b*Tt + Tt - 1))*Hh + j];
}

// ============================================================
extern "C" void kernel_launch(void* const* d_in, const int* in_sizes, int n_in,
                              void* d_out, int out_size)
{
    const int*   inputs = (const int*)  d_in[0];
    const float* emb    = (const float*)d_in[1];
    const float* W_ih   = (const float*)d_in[2];
    const float* W_hh   = (const float*)d_in[3];
    const float* b_ih   = (const float*)d_in[4];
    const float* b_hh   = (const float*)d_in[5];
    const float* W1     = (const float*)d_in[6];
    const float* b1     = (const float*)d_in[7];
    const float* W2     = (const float*)d_in[8];
    const float* b2     = (const float*)d_in[9];
    float* out = (float*)d_out;

    float *p_gi;
    __nv_bfloat16 *p_W1b, *p_W2b, *p_hsb, *p_yb;
    cudaGetSymbolAddress((void**)&p_gi,  g_gi);
    cudaGetSymbolAddress((void**)&p_W1b, g_W1b);
    cudaGetSymbolAddress((void**)&p_W2b, g_W2b);
    cudaGetSymbolAddress((void**)&p_hsb, g_hsb);
    cudaGetSymbolAddress((void**)&p_yb,  g_yb);

    cudaFuncSetAttribute(gru_persistent_kernel,
                         cudaFuncAttributeMaxDynamicSharedMemorySize, GRU_SMEM);
    cudaFuncSetAttribute(hmma_gemm_kernel,
                         cudaFuncAttributeMaxDynamicSharedMemorySize, HG_SMEM);

    // 0) weight -> bf16
    f2bf_kernel<<<(Hh*Hh)/1024, 256>>>(W1, p_W1b, (Hh*Hh)/4);
    f2bf_kernel<<<((size_t)Vv*Hh)/1024, 256>>>(W2, p_W2b, (Vv*Hh)/4);

    // 1) gi = gather(emb) @ W_ih^T + b_ih  (fp32)
    {
        dim3 grid(G3/128, Mm/128);
        sgemm_kernel<<<grid, 256>>>(emb, W_ih, b_ih, p_gi, Mm, G3, Ee, inputs, 0);
    }

    // 2) GRU scan (flags reset first for graph-replay determinism)
    gru_reset_kernel<<<1, GRU_BLOCKS>>>();
    gru_persistent_kernel<<<GRU_BLOCKS, GRU_THREADS, GRU_SMEM>>>(W_hh, b_hh);

    // 3) y = relu(hs @ W1^T + b1) -> bf16
    {
        dim3 grid(Hh/128, Mm/128);
        hmma_gemm_kernel<<<grid, 256, HG_SMEM>>>(p_hsb, p_W1b, b1, p_yb, Mm, Hh, Hh, 1, 1);
    }

    // 4) logits + fused softmax partials
    {
        dim3 grid(Vv/128, Mm/128);
        hmma_gemm_kernel<<<grid, 256, HG_SMEM>>>(p_yb, p_W2b, b2, out, Mm, Vv, Hh, 0, 0);
    }

    // 5) lse combine + exp-free subtract
    lse_reduce_kernel<<<Mm, 256>>>();
    {
        const size_t n4 = (size_t)Mm * Vv / 4;
        sub_kernel<<<(int)((n4 + 255) / 256), 256>>>(out);
    }

    // 6) hidden
    hidden_copy_kernel<<<(Bb*Hh)/256, 256>>>(out);
}

// round 17
// speedup vs baseline: 1.4601x; 1.0612x over previous
#include <cuda_runtime.h>
#include <cuda_bf16.h>
#include <math.h>
#include <cstdint>

#define Bb 16
#define Tt 256
#define Ee 512
#define E3 1536              // split-precision K = 3*Ee
#define Hh 1024
#define Vv 32000
#define G3 3072
#define Mm (Bb*Tt)   // 4096

#define GRU_BLOCKS 128
#define GRU_THREADS 512
#define NPART 500
#define NPART_PAD 512

// GEMM output modes
#define MODE_F32_SM   0   // fp32 out + fused softmax partials (decoder)
#define MODE_BF16RELU 1   // bf16 out + relu (lin1)
#define MODE_F32      2   // fp32 out, no partials (gi)

// ---- scratch ----
__device__ float g_gi[(size_t)Mm*G3];
__device__ float g_hs[(size_t)Mm*Hh];
__device__ float g_lse[Mm];
__device__ float2 g_part[(size_t)Mm*NPART_PAD];
__device__ __nv_bfloat16 g_W1b[(size_t)Hh*Hh];
__device__ __nv_bfloat16 g_W2b[(size_t)Vv*Hh];
__device__ __nv_bfloat16 g_Wihb2[(size_t)G3*E3];   // [W_hi | W_hi | W_lo]
__device__ __nv_bfloat16 g_xb2 [(size_t)Mm*E3];    // [x_hi | x_lo | x_hi]
__device__ __nv_bfloat16 g_hsb[(size_t)Mm*Hh];
__device__ __nv_bfloat16 g_yb [(size_t)Mm*Hh];
__device__ int g_flags[GRU_BLOCKS * 8];

__device__ __forceinline__ uint32_t smem_u32(const void* p) {
    uint32_t a;
    asm("{ .reg .u64 t; cvta.to.shared.u64 t, %1; cvt.u32.u64 %0, t; }" : "=r"(a) : "l"(p));
    return a;
}
__device__ __forceinline__ void fma2(unsigned long long& d, unsigned long long a, unsigned long long b) {
    asm("fma.rn.f32x2 %0, %1, %2, %0;" : "+l"(d) : "l"(a), "l"(b));
}
__device__ __forceinline__ float sum2(unsigned long long v) {
    float lo, hi;
    asm("mov.b64 {%0, %1}, %2;" : "=f"(lo), "=f"(hi) : "l"(v));
    return lo + hi;
}
__device__ __forceinline__ unsigned long long pack2(float lo, float hi) {
    unsigned long long v;
    asm("mov.b64 %0, {%1, %2};" : "=l"(v) : "f"(lo), "f"(hi));
    return v;
}

// ================= fp32 -> bf16 (weights) =================
__global__ void f2bf_kernel(const float* __restrict__ x, __nv_bfloat16* __restrict__ o, int n4)
{
    int i = blockIdx.x * blockDim.x + threadIdx.x;
    if (i >= n4) return;
    float4 v = ((const float4*)x)[i];
    __nv_bfloat162* p = (__nv_bfloat162*)o + i * 2;
    p[0] = __floats2bfloat162_rn(v.x, v.y);
    p[1] = __floats2bfloat162_rn(v.z, v.w);
}

// ---- split helpers ----
__device__ __forceinline__ void split2(float a, float b,
                                       __nv_bfloat162& hi, __nv_bfloat162& lo)
{
    const __nv_bfloat16 ah = __float2bfloat16_rn(a);
    const __nv_bfloat16 bh = __float2bfloat16_rn(b);
    hi = __nv_bfloat162(ah, bh);
    lo = __floats2bfloat162_rn(a - __bfloat162float(ah), b - __bfloat162float(bh));
}

// ================= W_ih split: B2 = [W_hi | W_hi | W_lo] =================
__global__ void wih_split_kernel(const float* __restrict__ W)
{
    const int idx = blockIdx.x * blockDim.x + threadIdx.x;   // float4 chunk
    if (idx >= G3 * (Ee/4)) return;
    const int row = idx >> 7;
    const int c   = idx & 127;
    const float4 v = ((const float4*)(W + (size_t)row * Ee))[c];
    __nv_bfloat162 h0, l0, h1, l1;
    split2(v.x, v.y, h0, l0);
    split2(v.z, v.w, h1, l1);
    __nv_bfloat16* base = g_Wihb2 + (size_t)row * E3;
    ((__nv_bfloat162*)base)[c*2]              = h0;
    ((__nv_bfloat162*)base)[c*2+1]            = h1;
    ((__nv_bfloat162*)(base + Ee))[c*2]       = h0;
    ((__nv_bfloat162*)(base + Ee))[c*2+1]     = h1;
    ((__nv_bfloat162*)(base + 2*Ee))[c*2]     = l0;
    ((__nv_bfloat162*)(base + 2*Ee))[c*2+1]   = l1;
}

// ================= gather+split x: A2 = [x_hi | x_lo | x_hi]; resets flags =================
__global__ void gather_split_kernel(const float* __restrict__ emb,
                                    const int* __restrict__ inputs)
{
    if (blockIdx.x == 0 && threadIdx.x < GRU_BLOCKS)
        g_flags[threadIdx.x * 8] = 0;
    const int idx = blockIdx.x * blockDim.x + threadIdx.x;   // float4 chunk
    if (idx >= Mm * (Ee/4)) return;
    const int row = idx >> 7;
    const int c   = idx & 127;
    const float4 v = ((const float4*)(emb + (size_t)inputs[row] * Ee))[c];
    __nv_bfloat162 h0, l0, h1, l1;
    split2(v.x, v.y, h0, l0);
    split2(v.z, v.w, h1, l1);
    __nv_bfloat16* base = g_xb2 + (size_t)row * E3;
    ((__nv_bfloat162*)base)[c*2]              = h0;
    ((__nv_bfloat162*)base)[c*2+1]            = h1;
    ((__nv_bfloat162*)(base + Ee))[c*2]       = l0;
    ((__nv_bfloat162*)(base + Ee))[c*2+1]     = l1;
    ((__nv_bfloat162*)(base + 2*Ee))[c*2]     = h0;
    ((__nv_bfloat162*)(base + 2*Ee))[c*2+1]   = h1;
}

// ================= HMMA bf16 GEMM, 3-stage cp.async =================
#define HG_STRIDE  40
#define HG_ATILE   (128 * HG_STRIDE * 2)
#define HG_STAGE   (2 * HG_ATILE)
#define HG_NSTG    3
#define HG_SMEM    (HG_NSTG * HG_STAGE)

__device__ __forceinline__ void ldsm_x4(uint32_t* r, uint32_t addr) {
    asm volatile("ldmatrix.sync.aligned.m8n8.x4.shared.b16 {%0,%1,%2,%3}, [%4];"
                 : "=r"(r[0]), "=r"(r[1]), "=r"(r[2]), "=r"(r[3]) : "r"(addr));
}
__device__ __forceinline__ void mma16816(float* d, const uint32_t* a, uint32_t b0, uint32_t b1) {
    asm volatile("mma.sync.aligned.m16n8k16.row.col.f32.bf16.bf16.f32 "
                 "{%0,%1,%2,%3}, {%4,%5,%6,%7}, {%8,%9}, {%0,%1,%2,%3};"
                 : "+f"(d[0]), "+f"(d[1]), "+f"(d[2]), "+f"(d[3])
                 : "r"(a[0]), "r"(a[1]), "r"(a[2]), "r"(a[3]), "r"(b0), "r"(b1));
}
__device__ __forceinline__ void cp_async16(uint32_t saddr, const void* gaddr) {
    asm volatile("cp.async.cg.shared.global [%0], [%1], 16;" :: "r"(saddr), "l"(gaddr));
}

__global__ void __launch_bounds__(256) hmma_gemm_kernel(
    const __nv_bfloat16* __restrict__ A,
    const __nv_bfloat16* __restrict__ Bm,
    const float* __restrict__ bias,
    void* __restrict__ Cv,
    int M, int N, int K, int mode)
{
    extern __shared__ char smem[];
    const uint32_t sb = smem_u32(smem);
    const int tid  = threadIdx.x;
    const int wid  = tid >> 5;
    const int lane = tid & 31;
    const int bn = blockIdx.x, bm = blockIdx.y;

    const int warp_m = wid & 3;
    const int warp_n = wid >> 2;

    float d[2][8][4];
#pragma unroll
    for (int i = 0; i < 2; i++)
#pragma unroll
        for (int j = 0; j < 8; j++)
#pragma unroll
            for (int q = 0; q < 4; q++) d[i][j][q] = 0.f;

    const int NK = K >> 5;
    const int lmat = lane >> 3;
    const int lrow = lane & 7;

    auto load_stage = [&](int it, int buf) {
        const int kt = it << 5;
        const uint32_t sa = sb + buf * HG_STAGE;
        const uint32_t sbB = sa + HG_ATILE;
#pragma unroll
        for (int s = 0; s < 2; s++) {
            const int idx = tid + s * 256;
            const int row = idx >> 2, c = idx & 3;
            cp_async16(sa + row * (HG_STRIDE*2) + c * 16,
                       A + (size_t)(bm * 128 + row) * K + kt + c * 8);
            cp_async16(sbB + row * (HG_STRIDE*2) + c * 16,
                       Bm + (size_t)(bn * 128 + row) * K + kt + c * 8);
        }
        asm volatile("cp.async.commit_group;");
    };

    load_stage(0, 0);
    load_stage(1, 1);

    for (int it = 0; it < NK; it++) {
        asm volatile("cp.async.wait_group 1;");
        __syncthreads();
        if (it + 2 < NK) load_stage(it + 2, (it + 2) % HG_NSTG);

        const uint32_t sa  = sb + (it % HG_NSTG) * HG_STAGE;
        const uint32_t sbB = sa + HG_ATILE;

#pragma unroll
        for (int ks = 0; ks < 2; ks++) {
            uint32_t a[2][4];
#pragma unroll
            for (int mt = 0; mt < 2; mt++) {
                const int row = warp_m * 32 + mt * 16 + (lmat & 1) * 8 + lrow;
                const int c   = ks * 2 + (lmat >> 1);
                ldsm_x4(a[mt], sa + row * (HG_STRIDE*2) + c * 16);
            }
            uint32_t b[4][4];
#pragma unroll
            for (int nt = 0; nt < 4; nt++) {
                const int n = warp_n * 64 + nt * 16 + (lmat >> 1) * 8 + lrow;
                const int c = ks * 2 + (lmat & 1);
                ldsm_x4(b[nt], sbB + n * (HG_STRIDE*2) + c * 16);
            }
#pragma unroll
            for (int mt = 0; mt < 2; mt++)
#pragma unroll
                for (int nt = 0; nt < 4; nt++) {
                    mma16816(d[mt][nt*2+0], a[mt], b[nt][0], b[nt][1]);
                    mma16816(d[mt][nt*2+1], a[mt], b[nt][2], b[nt][3]);
                }
        }
    }

#pragma unroll
    for (int mt = 0; mt < 2; mt++) {
        const int row0 = bm * 128 + warp_m * 32 + mt * 16 + (lane >> 2);
#pragma unroll
        for (int nt8 = 0; nt8 < 8; nt8++) {
            const int col = bn * 128 + warp_n * 64 + nt8 * 8 + (lane & 3) * 2;
            const float b0 = bias[col], b1 = bias[col + 1];
            float2 v0, v1;
            v0.x = d[mt][nt8][0] + b0; v0.y = d[mt][nt8][1] + b1;
            v1.x = d[mt][nt8][2] + b0; v1.y = d[mt][nt8][3] + b1;
            if (mode == MODE_BF16RELU) {
                v0.x = fmaxf(v0.x, 0.f); v0.y = fmaxf(v0.y, 0.f);
                v1.x = fmaxf(v1.x, 0.f); v1.y = fmaxf(v1.y, 0.f);
                __nv_bfloat162* C = (__nv_bfloat162*)Cv;
                C[((size_t)row0 * N + col) >> 1]       = __floats2bfloat162_rn(v0.x, v0.y);
                C[((size_t)(row0 + 8) * N + col) >> 1] = __floats2bfloat162_rn(v1.x, v1.y);
            } else {
                float* C = (float*)Cv;
                *(float2*)(C + (size_t)row0 * N + col)       = v0;
                *(float2*)(C + (size_t)(row0 + 8) * N + col) = v1;
            }
        }
    }

    if (mode == MODE_F32_SM) {
        const int colt = bn * 128 + warp_n * 64 + (lane & 3) * 2;
#pragma unroll
        for (int mt = 0; mt < 2; mt++) {
            const int rowb = bm * 128 + warp_m * 32 + mt * 16 + (lane >> 2);
#pragma unroll
            for (int half = 0; half < 2; half++) {
                float mx = -INFINITY;
#pragma unroll
                for (int nt8 = 0; nt8 < 8; nt8++) {
                    const float v0 = d[mt][nt8][half*2+0] + bias[colt + nt8*8];
                    const float v1 = d[mt][nt8][half*2+1] + bias[colt + nt8*8 + 1];
                    mx = fmaxf(mx, fmaxf(v0, v1));
                }
                float s = 0.f;
#pragma unroll
                for (int nt8 = 0; nt8 < 8; nt8++) {
                    const float v0 = d[mt][nt8][half*2+0] + bias[colt + nt8*8];
                    const float v1 = d[mt][nt8][half*2+1] + bias[colt + nt8*8 + 1];
                    s += __expf(v0 - mx) + __expf(v1 - mx);
                }
#pragma unroll
                for (int o = 1; o <= 2; o <<= 1) {
                    const float m2 = __shfl_xor_sync(0xffffffffu, mx, o);
                    const float s2 = __shfl_xor_sync(0xffffffffu, s, o);
                    const float M_ = fmaxf(mx, m2);
                    s = s * __expf(mx - M_) + s2 * __expf(m2 - M_);
                    mx = M_;
                }
                if ((lane & 3) == 0) {
                    const int row = rowb + half * 8;
                    g_part[(size_t)row * NPART_PAD + bn * 2 + warp_n] = make_float2(mx, s);
                }
            }
        }
    }
}

// ================= GRU v2 (unchanged) =================
#define HT_PAD    34
#define HT_FLOATS (512*HT_PAD)
#define GRU_SMEM  ((24*1024 + HT_FLOATS + 8*3*16) * 4)

__global__ void __launch_bounds__(GRU_THREADS) gru_persistent_kernel(
    const float* __restrict__ W_hh,
    const float* __restrict__ b_hh)
{
    extern __shared__ float smf[];
    float* W_s = smf;
    float* hT  = smf + 24*1024;
    float* cmb = hT + HT_FLOATS;

    const int tid  = threadIdx.x;
    const int wid  = tid >> 5;
    const int lane = tid & 31;
    const int blk  = blockIdx.x;
    const int jj   = wid & 7;
    const int kh   = wid >> 3;
    const int j    = blk * 8 + jj;
    const int b    = lane & 15;
    const int ks   = lane >> 4;
    const int k0   = kh * 512 + ks * 256;

    for (int idx = tid; idx < 24*256; idx += GRU_THREADS) {
        const int r = idx >> 8;
        const int q = idx & 255;
        const int gate = r >> 3, wr = r & 7;
        *(float4*)&W_s[r*1024 + q*4] =
            *(const float4*)&W_hh[((size_t)(gate*Hh + blk*8 + wr))*Hh + q*4];
    }
    for (int i = tid; i < HT_FLOATS; i += GRU_THREADS) hT[i] = 0.f;
    __syncthreads();

    const float* wr_s = W_s + (0*8 + jj) * 1024;
    const float* wz_s = W_s + (1*8 + jj) * 1024;
    const float* wn_s = W_s + (2*8 + jj) * 1024;

    float bhr = 0.f, bhz = 0.f, bhn = 0.f;
    if (kh == 0 && lane < 16) {
        bhr = b_hh[j]; bhz = b_hh[j + Hh]; bhn = b_hh[j + 2*Hh];
    }

    for (int t = 0; t < Tt; t++) {
        float ir = 0.f, iz = 0.f, inn = 0.f;
        if (kh == 0 && lane < 16) {
            const float* gi = g_gi + ((size_t)(b*Tt + t)) * G3;
            ir  = __ldcg(gi + j);
            iz  = __ldcg(gi + j + Hh);
            inn = __ldcg(gi + j + 2*Hh);
        }

        unsigned long long accr = 0ull, accz = 0ull, accn = 0ull;
        const float* hrow = hT + b*2;
#pragma unroll 8
        for (int kk = 0; kk < 256; kk += 4) {
            const int k = k0 + kk;
            const float4 wr4 = *(const float4*)&wr_s[k];
            const float4 wz4 = *(const float4*)&wz_s[k];
            const float4 wn4 = *(const float4*)&wn_s[k];
            const unsigned long long h01 = *(const unsigned long long*)&hrow[(k>>1)*HT_PAD];
            const unsigned long long h23 = *(const unsigned long long*)&hrow[((k>>1)+1)*HT_PAD];
            fma2(accr, pack2(wr4.x, wr4.y), h01);
            fma2(accz, pack2(wz4.x, wz4.y), h01);
            fma2(accn, pack2(wn4.x, wn4.y), h01);
            fma2(accr, pack2(wr4.z, wr4.w), h23);
            fma2(accz, pack2(wz4.z, wz4.w), h23);
            fma2(accn, pack2(wn4.z, wn4.w), h23);
        }
        float sr = sum2(accr), sz = sum2(accz), sn = sum2(accn);
        sr += __shfl_xor_sync(0xffffffffu, sr, 16);
        sz += __shfl_xor_sync(0xffffffffu, sz, 16);
        sn += __shfl_xor_sync(0xffffffffu, sn, 16);

        if (kh == 1 && lane < 16) {
            cmb[(jj*3 + 0)*16 + b] = sr;
            cmb[(jj*3 + 1)*16 + b] = sz;
            cmb[(jj*3 + 2)*16 + b] = sn;
        }
        __syncthreads();

        if (kh == 0 && lane < 16) {
            sr += cmb[(jj*3 + 0)*16 + b];
            sz += cmb[(jj*3 + 1)*16 + b];
            sn += cmb[(jj*3 + 2)*16 + b];
            const float r = 1.f / (1.f + expf(-(ir + sr + bhr)));
            const float z = 1.f / (1.f + expf(-(iz + sz + bhz)));
            const float n = tanhf(inn + r * (sn + bhn));
            const float hp = hT[(j>>1)*HT_PAD + b*2 + (j&1)];
            const float h_new = (1.f - z)*n + z*hp;
            g_hs [((size_t)(b*Tt + t))*Hh + j] = h_new;
            g_hsb[((size_t)(b*Tt + t))*Hh + j] = __float2bfloat16(h_new);
        }

        if (t + 1 < Tt) {
            __syncthreads();
            if (tid == 0) {
                __threadfence();
                *(volatile int*)&g_flags[blk * 8] = t + 1;
            }
            if (tid < GRU_BLOCKS) {
                while (*(volatile int*)&g_flags[tid * 8] < t + 1) __nanosleep(32);
                __threadfence();
            }
            __syncthreads();
            const float* src = &g_hs[((size_t)(wid*Tt + t))*Hh];
#pragma unroll
            for (int it = 0; it < 8; it++) {
                const int j4 = lane + it*32;
                const float4 v = __ldcg((const float4*)src + j4);
                *(float2*)&hT[(j4*2)*HT_PAD   + wid*2] = make_float2(v.x, v.y);
                *(float2*)&hT[(j4*2+1)*HT_PAD + wid*2] = make_float2(v.z, v.w);
            }
            __syncthreads();
        }
    }
}

// ================= lse reduce + subtract =================
__global__ void __launch_bounds__(256) lse_reduce_kernel()
{
    const int row = blockIdx.x;
    const int tid = threadIdx.x;
    float m = -INFINITY, s = 0.f;
    for (int i = tid; i < NPART; i += 256) {
        const float2 p = g_part[(size_t)row * NPART_PAD + i];
        const float M_ = fmaxf(m, p.x);
        s = s * __expf(m - M_) + p.y * __expf(p.x - M_);
        m = M_;
    }
    __shared__ float sm[256], ss[256];
    sm[tid] = m; ss[tid] = s;
    __syncthreads();
    for (int o = 128; o > 0; o >>= 1) {
        if (tid < o) {
            const float m2 = sm[tid + o], s2 = ss[tid + o];
            const float M_ = fmaxf(sm[tid], m2);
            ss[tid] = ss[tid]*__expf(sm[tid]-M_) + s2*__expf(m2-M_);
            sm[tid] = M_;
        }
        __syncthreads();
    }
    if (tid == 0) g_lse[row] = sm[0] + logf(ss[0]);
}

__global__ void sub_kernel(float* __restrict__ out)
{
    const size_t i = (size_t)blockIdx.x * blockDim.x + threadIdx.x;
    const size_t n4 = (size_t)Mm * Vv / 4;
    if (i >= n4) return;
    const int row = (int)((i * 4) / Vv);
    const float l = g_lse[row];
    float4 v = ((float4*)out)[i];
    v.x -= l; v.y -= l; v.z -= l; v.w -= l;
    ((float4*)out)[i] = v;
}

__global__ void hidden_copy_kernel(float* __restrict__ out)
{
    const int i = blockIdx.x * blockDim.x + threadIdx.x;
    const int b = i >> 10;
    const int j = i & (Hh - 1);
    out[(size_t)Mm*Vv + i] = g_hs[((size_t)(b*Tt + Tt - 1))*Hh + j];
}

// ============================================================
extern "C" void kernel_launch(void* const* d_in, const int* in_sizes, int n_in,
                              void* d_out, int out_size)
{
    const int*   inputs = (const int*)  d_in[0];
    const float* emb    = (const float*)d_in[1];
    const float* W_ih   = (const float*)d_in[2];
    const float* W_hh   = (const float*)d_in[3];
    const float* b_ih   = (const float*)d_in[4];
    const float* b_hh   = (const float*)d_in[5];
    const float* W1     = (const float*)d_in[6];
    const float* b1     = (const float*)d_in[7];
    const float* W2     = (const float*)d_in[8];
    const float* b2     = (const float*)d_in[9];
    float* out = (float*)d_out;

    float *p_gi;
    __nv_bfloat16 *p_W1b, *p_W2b, *p_Wihb2, *p_xb2, *p_hsb, *p_yb;
    cudaGetSymbolAddress((void**)&p_gi,    g_gi);
    cudaGetSymbolAddress((void**)&p_W1b,   g_W1b);
    cudaGetSymbolAddress((void**)&p_W2b,   g_W2b);
    cudaGetSymbolAddress((void**)&p_Wihb2, g_Wihb2);
    cudaGetSymbolAddress((void**)&p_xb2,   g_xb2);
    cudaGetSymbolAddress((void**)&p_hsb,   g_hsb);
    cudaGetSymbolAddress((void**)&p_yb,    g_yb);

    cudaFuncSetAttribute(gru_persistent_kernel,
                         cudaFuncAttributeMaxDynamicSharedMemorySize, GRU_SMEM);
    cudaFuncSetAttribute(hmma_gemm_kernel,
                         cudaFuncAttributeMaxDynamicSharedMemorySize, HG_SMEM);

    // 0) conversions
    f2bf_kernel<<<(Hh*Hh)/1024, 256>>>(W1, p_W1b, (Hh*Hh)/4);
    f2bf_kernel<<<((size_t)Vv*Hh)/1024, 256>>>(W2, p_W2b, (Vv*Hh)/4);
    wih_split_kernel<<<(G3*(Ee/4))/256, 256>>>(W_ih);
    gather_split_kernel<<<(Mm*(Ee/4))/256, 256>>>(emb, inputs);

    // 1) gi = [x_hi|x_lo|x_hi] @ [W_hi|W_hi|W_lo]^T + b_ih   (split-precision HMMA, K=1536)
    {
        dim3 grid(G3/128, Mm/128);
        hmma_gemm_kernel<<<grid, 256, HG_SMEM>>>(p_xb2, p_Wihb2, b_ih, p_gi,
                                                 Mm, G3, E3, MODE_F32);
    }

    // 2) GRU scan
    gru_persistent_kernel<<<GRU_BLOCKS, GRU_THREADS, GRU_SMEM>>>(W_hh, b_hh);

    // 3) y = relu(hs @ W1^T + b1) -> bf16
    {
        dim3 grid(Hh/128, Mm/128);
        hmma_gemm_kernel<<<grid, 256, HG_SMEM>>>(p_hsb, p_W1b, b1, p_yb,
                                                 Mm, Hh, Hh, MODE_BF16RELU);
    }

    // 4) logits + fused softmax partials
    {
        dim3 grid(Vv/128, Mm/128);
        hmma_gemm_kernel<<<grid, 256, HG_SMEM>>>(p_yb, p_W2b, b2, out,
                                                 Mm, Vv, Hh, MODE_F32_SM);
    }

    // 5) lse combine + exp-free subtract
    lse_reduce_kernel<<<Mm, 256>>>();
    {
        const size_t n4 = (size_t)Mm * Vv / 4;
        sub_kernel<<<(int)((n4 + 255) / 256), 256>>>(out);
    }

    // 6) hidden
    hidden_copy_kernel<<<(Bb*Hh)/256, 256>>>(out);
}